// round 5
// baseline (speedup 1.0000x reference)
#include <cuda_runtime.h>
#include <cstdint>
#include <cstddef>

#define BB   2
#define NN   1024
#define DN   128
#define DE   16
#define MIDC 64
#define OUTC 128

// ---------------- scratch (static device arrays; no allocs) ----------------
__device__ __align__(16) float g_p1  [BB*NN*MIDC];   // features @ W1                 (per-j)
__device__ __align__(16) float g_base[BB*NN*MIDC];   // features @ W2 + all biases + g@Wg (per-i)
__device__ __align__(16) float g_vals[BB*NN*OUTC];   // features @ Wm + bm
__device__ __align__(16) float g_skip[BB*NN*OUTC];   // features @ Wskip + bskip
__device__ float g_gw [BB*MIDC];                     // g_features @ Wg
__device__ float g_t  [BB*NN];                       // 0.505 * (p1_row . Wa)
__device__ float g_s2 [BB*NN];                       // ba + 0.505 * (base_row . Wa)
__device__ __align__(16) float g_wea[16];            // 0.505 * (We @ Wa)
__device__ __align__(16) float g_logits[BB*NN*NN];   // masked logits (8MB, L2-resident)
__device__ float g_rowmax[BB*NN];                    // per-row max of masked logits

typedef unsigned long long ull;

// ---------------- helpers ----------------
__device__ __forceinline__ uint32_t f2tf(float x) {
    uint32_t r; asm("cvt.rna.tf32.f32 %0, %1;" : "=r"(r) : "f"(x)); return r;
}
__device__ __forceinline__ ull pk2(float x, float y) {
    ull r; asm("mov.b64 %0, {%1, %2};" : "=l"(r) : "f"(x), "f"(y)); return r;
}
__device__ __forceinline__ ull dup2(float c) {
    ull r; asm("mov.b64 %0, {%1, %1};" : "=l"(r) : "f"(c)); return r;
}
__device__ __forceinline__ float2 upk(ull v) {
    float2 f; asm("mov.b64 {%0, %1}, %2;" : "=f"(f.x), "=f"(f.y) : "l"(v)); return f;
}
__device__ __forceinline__ void fma_x2(ull& d, ull a, ull b) {
    asm("fma.rn.f32x2 %0, %1, %2, %0;" : "+l"(d) : "l"(a), "l"(b));
}
__device__ __forceinline__ ull add_x2(ull a, ull b) {
    ull d; asm("add.rn.f32x2 %0, %1, %2;" : "=l"(d) : "l"(a), "l"(b)); return d;
}
__device__ __forceinline__ ull abs_x2(ull x) {
    ull r; asm("and.b64 %0, %1, 0x7FFFFFFF7FFFFFFF;" : "=l"(r) : "l"(x)); return r;
}
// m16n8k8 tf32 MMA on packed accumulators (c01 = row qid, c23 = row qid+8)
__device__ __forceinline__ void mma_p(ull& c01, ull& c23,
                                      const uint32_t a[4], uint32_t b0, uint32_t b1) {
    asm volatile("{\n\t"
        ".reg .f32 f0,f1,f2,f3;\n\t"
        "mov.b64 {f0,f1}, %0;\n\t"
        "mov.b64 {f2,f3}, %1;\n\t"
        "mma.sync.aligned.m16n8k8.row.col.f32.tf32.tf32.f32 "
        "{f0,f1,f2,f3}, {%2,%3,%4,%5}, {%6,%7}, {f0,f1,f2,f3};\n\t"
        "mov.b64 %0, {f0,f1};\n\t"
        "mov.b64 %1, {f2,f3};\n\t"
        "}" : "+l"(c01), "+l"(c23)
            : "r"(a[0]), "r"(a[1]), "r"(a[2]), "r"(a[3]), "r"(b0), "r"(b1));
}

// ---------------- prep 0: g@Wg and We@Wa ----------------
__global__ void prep_g(const float* __restrict__ gf, const float* __restrict__ Wg,
                       const float* __restrict__ We, const float* __restrict__ Wa) {
    int b = blockIdx.x;
    int t = threadIdx.x;
    if (t < MIDC) {
        float acc = 0.f;
        #pragma unroll 8
        for (int c = 0; c < DN; ++c) acc = fmaf(gf[b*DN + c], Wg[c*MIDC + t], acc);
        g_gw[b*MIDC + t] = acc;
    } else if (b == 0 && t < MIDC + DE) {
        int c = t - MIDC;
        float acc = 0.f;
        #pragma unroll
        for (int m = 0; m < MIDC; ++m) acc = fmaf(We[c*MIDC + m], Wa[m], acc);
        g_wea[c] = 0.505f * acc;
    }
}

// ---------------- prep 1: per-node linear terms, 16 rows per CTA ----------------
// block 384: t<128 -> Wm col, t<256 -> Wskip col, t<320 -> W1 col, t<384 -> W2 col
__global__ __launch_bounds__(384) void prep_all(
    const float* __restrict__ feat,
    const float* __restrict__ Wm,   const float* __restrict__ bm,
    const float* __restrict__ Wsk,  const float* __restrict__ bsk,
    const float* __restrict__ W1,   const float* __restrict__ b1,
    const float* __restrict__ W2,   const float* __restrict__ b2,
    const float* __restrict__ be,   const float* __restrict__ bg)
{
    __shared__ float sF[16*DN];
    const int r0 = blockIdx.x * 16;        // global row (b*N + n)
    const int b  = r0 / NN;
    const int t  = threadIdx.x;
    for (int x = t; x < 16*DN; x += 384) sF[x] = feat[(size_t)r0*DN + x];
    __syncthreads();

    const float* W; int stride, col;
    if      (t < 128) { W = Wm;  stride = OUTC; col = t;       }
    else if (t < 256) { W = Wsk; stride = OUTC; col = t - 128; }
    else if (t < 320) { W = W1;  stride = MIDC; col = t - 256; }
    else              { W = W2;  stride = MIDC; col = t - 320; }
    const float* wp = W + col;

    float acc[16];
    #pragma unroll
    for (int r = 0; r < 16; ++r) acc[r] = 0.f;
    #pragma unroll 4
    for (int c = 0; c < DN; ++c) {
        float wv = __ldg(wp + c*stride);
        #pragma unroll
        for (int r = 0; r < 16; ++r) acc[r] = fmaf(sF[r*DN + c], wv, acc[r]);
    }

    if (t < 128) {
        float bb = bm[col];
        #pragma unroll
        for (int r = 0; r < 16; ++r) g_vals[(size_t)(r0+r)*OUTC + col] = acc[r] + bb;
    } else if (t < 256) {
        float bb = bsk[col];
        #pragma unroll
        for (int r = 0; r < 16; ++r) g_skip[(size_t)(r0+r)*OUTC + col] = acc[r] + bb;
    } else if (t < 320) {
        #pragma unroll
        for (int r = 0; r < 16; ++r) g_p1[(size_t)(r0+r)*MIDC + col] = acc[r];
    } else {
        float bb = b1[col] + b2[col] + be[col] + bg[col] + g_gw[b*MIDC + col];
        #pragma unroll
        for (int r = 0; r < 16; ++r) g_base[(size_t)(r0+r)*MIDC + col] = acc[r] + bb;
    }
}

// ---------------- prep 2: per-row scalar dots with Wa ----------------
__global__ __launch_bounds__(256) void prep_dots(const float* __restrict__ Wa,
                                                 const float* __restrict__ ba) {
    const int w    = threadIdx.x >> 5;
    const int lane = threadIdx.x & 31;
    const int row  = blockIdx.x * 8 + w;       // 0 .. BB*NN-1
    float2 wa2 = ((const float2*)Wa)[lane];
    float2 pa  = ((const float2*)(g_p1   + (size_t)row*MIDC))[lane];
    float2 bb  = ((const float2*)(g_base + (size_t)row*MIDC))[lane];
    float vp = fmaf(pa.y, wa2.y, pa.x*wa2.x);
    float vb = fmaf(bb.y, wa2.y, bb.x*wa2.x);
    #pragma unroll
    for (int o = 16; o >= 1; o >>= 1) {
        vp += __shfl_xor_sync(0xffffffffu, vp, o);
        vb += __shfl_xor_sync(0xffffffffu, vb, o);
    }
    if (lane == 0) {
        g_t [row] = 0.505f * vp;
        g_s2[row] = ba[0] + 0.505f * vb;
    }
}

// ---------------- kernel A: masked logits + row max ----------------
// grid (NN/8, BB), block 256 (8 warps), warp = one i-row. 2 CTAs/SM target.
__global__ __launch_bounds__(256, 2) void logits_kernel(
    const float* __restrict__ ef,   // (B,N,N,DE)
    const float* __restrict__ adj,  // (B,N,N)
    const float* __restrict__ We,   // (DE,MID)
    const float* __restrict__ Wa)   // (MID,1)
{
    __shared__ float sWaN[MIDC];    // 0.495 * Wa
    const int b    = blockIdx.y;
    const int tid  = threadIdx.x;
    const int w    = tid >> 5;
    const int lane = tid & 31;
    const int qid  = lane >> 2;
    const int qt   = lane & 3;
    const int i    = blockIdx.x*8 + w;

    if (tid < MIDC) sWaN[tid] = 0.495f * Wa[tid];
    __syncthreads();

    // We fragments under permutations (k: c = 4q+2s+h ; n: m = 16*qt' + 2*nt + r)
    uint32_t bf0[8][2], bf1[8][2];
    {
        const int colb = 16*(qid >> 1) + (qid & 1);
        #pragma unroll
        for (int nt = 0; nt < 8; ++nt) {
            bf0[nt][0] = f2tf(We[(4*qt + 0)*MIDC + colb + 2*nt]);
            bf0[nt][1] = f2tf(We[(4*qt + 1)*MIDC + colb + 2*nt]);
            bf1[nt][0] = f2tf(We[(4*qt + 2)*MIDC + colb + 2*nt]);
            bf1[nt][1] = f2tf(We[(4*qt + 3)*MIDC + colb + 2*nt]);
        }
    }
    ull bse[8];
    {
        const ull* bp = (const ull*)(g_base + (size_t)(b*NN + i)*MIDC);
        #pragma unroll
        for (int nt = 0; nt < 8; ++nt) bse[nt] = bp[8*qt + nt];
    }
    const float  sI   = g_s2[b*NN + i];
    const float4 wea  = ((const float4*)g_wea)[qt];
    const float* __restrict__ tb     = g_t + b*NN;
    const float* __restrict__ adjrow = adj + (size_t)(b*NN + i)*NN;
    const float4* __restrict__ er    = (const float4*)ef + (size_t)(b*NN + i)*NN*(DE/4);
    float* __restrict__ lrow         = g_logits + (size_t)(b*NN + i)*NN;

    // depth-1 prefetch of DRAM operands
    float4 eA = __ldg(er + (size_t)qid*(DE/4) + qt);
    float4 eB = __ldg(er + (size_t)(qid + 8)*(DE/4) + qt);
    float  ad0 = __ldg(adjrow + qid);
    float  ad1 = __ldg(adjrow + qid + 8);
    float  mx  = -3.0e38f;

    #pragma unroll 1
    for (int jt = 0; jt < NN/16; ++jt) {
        const int j0 = jt*16 + qid;
        const ull* r1a = (const ull*)(g_p1 + (size_t)(b*NN + j0    )*MIDC);
        const ull* r1b = (const ull*)(g_p1 + (size_t)(b*NN + j0 + 8)*MIDC);

        const int jb = (jt < NN/16 - 1) ? (jt+1)*16 + qid : j0;
        float4 nA = __ldg(er + (size_t)jb*(DE/4) + qt);
        float4 nB = __ldg(er + (size_t)(jb + 8)*(DE/4) + qt);
        float  nd0 = __ldg(adjrow + jb);
        float  nd1 = __ldg(adjrow + jb + 8);

        uint32_t aS0[4] = { f2tf(eA.x), f2tf(eB.x), f2tf(eA.y), f2tf(eB.y) };
        uint32_t aS1[4] = { f2tf(eA.z), f2tf(eB.z), f2tf(eA.w), f2tf(eB.w) };

        ull P0 = 0ull, P1 = 0ull;
        #pragma unroll
        for (int nt = 0; nt < 8; ++nt) {
            ull pa = r1a[8*qt + nt];
            ull pb = r1b[8*qt + nt];
            ull wn = ((const ull*)sWaN)[8*qt + nt];
            ull c01 = add_x2(bse[nt], pa);
            ull c23 = add_x2(bse[nt], pb);
            mma_p(c01, c23, aS0, bf0[nt][0], bf0[nt][1]);
            mma_p(c01, c23, aS1, bf1[nt][0], bf1[nt][1]);
            fma_x2(P0, wn, abs_x2(c01));
            fma_x2(P1, wn, abs_x2(c23));
        }
        float lin0 = fmaf(eA.w, wea.w, fmaf(eA.z, wea.z, fmaf(eA.y, wea.y, eA.x*wea.x)));
        float lin1 = fmaf(eB.w, wea.w, fmaf(eB.z, wea.z, fmaf(eB.y, wea.y, eB.x*wea.x)));
        float2 u0 = upk(P0), u1 = upk(P1);
        float acc0 = u0.x + u0.y + lin0;
        float acc1 = u1.x + u1.y + lin1;
        acc0 += __shfl_xor_sync(0xffffffffu, acc0, 1);
        acc0 += __shfl_xor_sync(0xffffffffu, acc0, 2);
        acc1 += __shfl_xor_sync(0xffffffffu, acc1, 1);
        acc1 += __shfl_xor_sync(0xffffffffu, acc1, 2);
        if (qt == 0) {
            float l0 = acc0 + sI + tb[j0]   + (ad0 - 1.0f)*1e9f;
            float l1 = acc1 + sI + tb[j0+8] + (ad1 - 1.0f)*1e9f;
            lrow[j0]     = l0;
            lrow[j0 + 8] = l1;
            mx = fmaxf(mx, fmaxf(l0, l1));
        }
        eA = nA; eB = nB; ad0 = nd0; ad1 = nd1;
    }
    // reduce max over the 8 qt==0 lanes (lanes 0,4,...,28)
    mx = fmaxf(mx, __shfl_xor_sync(0xffffffffu, mx, 4));
    mx = fmaxf(mx, __shfl_xor_sync(0xffffffffu, mx, 8));
    mx = fmaxf(mx, __shfl_xor_sync(0xffffffffu, mx, 16));
    if (lane == 0) g_rowmax[b*NN + i] = mx;
}

// ---------------- kernel B: exp/softmax + coefs@values + skip + relu ----------------
// grid (NN/16, BB), block 256 (8 warps, 2 rows/warp). smem: sE 64KB + sV 16KB (double-buffered).
__global__ __launch_bounds__(256) void aggregate_kernel(float* __restrict__ outp)
{
    extern __shared__ float smB[];
    float* sE = smB;                    // 16 * NN  exp values
    float* sV = smB + 16*NN;            // 2 * 16 * OUTC  value tiles
    const int b    = blockIdx.y;
    const int it0  = blockIdx.x * 16;
    const int tid  = threadIdx.x;
    const int w    = tid >> 5;
    const int lane = tid & 31;
    const int r0   = 2*w, r1 = 2*w + 1;

    // exp phase (warp-private rows; ordered vs reads by the __syncthreads below)
    float inv[2];
    #pragma unroll
    for (int il = 0; il < 2; ++il) {
        const int i = it0 + 2*w + il;
        const float mxv = g_rowmax[b*NN + i];
        const float4* lr = (const float4*)(g_logits + (size_t)(b*NN + i)*NN);
        float4* se = (float4*)(sE + (2*w + il)*NN);
        float s = 0.f;
        #pragma unroll
        for (int t = 0; t < 8; ++t) {
            float4 L = __ldg(lr + lane + 32*t);
            float4 E;
            E.x = __expf(L.x - mxv); E.y = __expf(L.y - mxv);
            E.z = __expf(L.z - mxv); E.w = __expf(L.w - mxv);
            se[lane + 32*t] = E;
            s += (E.x + E.y) + (E.z + E.w);
        }
        #pragma unroll
        for (int o = 16; o >= 1; o >>= 1) s += __shfl_xor_sync(0xffffffffu, s, o);
        inv[il] = 1.0f / s;
    }

    // aggregation with double-buffered value tiles (16 j x 128 ch per tile)
    const float4* v4 = (const float4*)g_vals + (size_t)b*NN*(OUTC/4);
    {
        #pragma unroll
        for (int k = 0; k < 2; ++k) {
            int f = 2*tid + k; int jr = f >> 5, fc = f & 31;
            ((float4*)sV)[f] = __ldg(v4 + (size_t)jr*(OUTC/4) + fc);
        }
    }
    __syncthreads();

    ull a00 = 0ull, a01 = 0ull, a10 = 0ull, a11 = 0ull;
    #pragma unroll 1
    for (int jt = 0; jt < NN/16; ++jt) {
        const int cur = jt & 1;
        float4 pre0, pre1;
        if (jt < NN/16 - 1) {
            int f0 = 2*tid, f1 = 2*tid + 1;
            pre0 = __ldg(v4 + (size_t)((jt+1)*16 + (f0 >> 5))*(OUTC/4) + (f0 & 31));
            pre1 = __ldg(v4 + (size_t)((jt+1)*16 + (f1 >> 5))*(OUTC/4) + (f1 & 31));
        }
        const float* e0p = sE + r0*NN + jt*16;
        const float* e1p = sE + r1*NN + jt*16;
        const float4* vb = (const float4*)(sV + cur*(16*OUTC));
        #pragma unroll
        for (int jj = 0; jj < 16; ++jj) {
            float4 v = vb[jj*(OUTC/4) + lane];
            ull v01 = pk2(v.x, v.y), v23 = pk2(v.z, v.w);
            ull c0 = dup2(e0p[jj]);
            ull c1 = dup2(e1p[jj]);
            fma_x2(a00, v01, c0);  fma_x2(a01, v23, c0);
            fma_x2(a10, v01, c1);  fma_x2(a11, v23, c1);
        }
        if (jt < NN/16 - 1) {
            float4* dst = (float4*)(sV + (cur ^ 1)*(16*OUTC));
            dst[2*tid]     = pre0;
            dst[2*tid + 1] = pre1;
            __syncthreads();
        }
    }

    // epilogue
    #pragma unroll
    for (int il = 0; il < 2; ++il) {
        size_t row = (size_t)(b*NN + it0 + 2*w + il);
        float2 x0 = upk(il ? a10 : a00);
        float2 x1 = upk(il ? a11 : a01);
        float4 sk = __ldg((const float4*)g_skip + row*(OUTC/4) + lane);
        float4 o;
        o.x = fmaxf(fmaf(x0.x, inv[il], sk.x), 0.f);
        o.y = fmaxf(fmaf(x0.y, inv[il], sk.y), 0.f);
        o.z = fmaxf(fmaf(x1.x, inv[il], sk.z), 0.f);
        o.w = fmaxf(fmaf(x1.y, inv[il], sk.w), 0.f);
        ((float4*)outp)[row*(OUTC/4) + lane] = o;
    }
}

// ---------------- launch ----------------
extern "C" void kernel_launch(void* const* d_in, const int* in_sizes, int n_in,
                              void* d_out, int out_size)
{
    const float* features   = (const float*)d_in[0];
    const float* e_features = (const float*)d_in[1];
    const float* g_features = (const float*)d_in[2];
    const float* adj        = (const float*)d_in[3];
    const float* Wm         = (const float*)d_in[4];
    const float* bm         = (const float*)d_in[5];
    const float* Wskip      = (const float*)d_in[6];
    const float* bskip      = (const float*)d_in[7];
    const float* W1         = (const float*)d_in[8];
    const float* b1         = (const float*)d_in[9];
    const float* W2         = (const float*)d_in[10];
    const float* b2         = (const float*)d_in[11];
    const float* We         = (const float*)d_in[12];
    const float* be         = (const float*)d_in[13];
    const float* Wg         = (const float*)d_in[14];
    const float* bg         = (const float*)d_in[15];
    const float* Wa         = (const float*)d_in[16];
    const float* ba         = (const float*)d_in[17];
    float* outp = (float*)d_out;

    const int smemB = (16*NN + 2*16*OUTC) * (int)sizeof(float);   // 81920
    cudaFuncSetAttribute(aggregate_kernel, cudaFuncAttributeMaxDynamicSharedMemorySize, smemB);

    prep_g   <<<BB, MIDC + DE + 16>>>(g_features, Wg, We, Wa);
    prep_all <<<BB*NN/16, 384>>>(features, Wm, bm, Wskip, bskip, W1, b1, W2, b2, be, bg);
    prep_dots<<<BB*NN/8, 256>>>(Wa, ba);

    dim3 gridA(NN/8, BB);
    logits_kernel<<<gridA, 256>>>(e_features, adj, We, Wa);

    dim3 gridB(NN/16, BB);
    aggregate_kernel<<<gridB, 256, smemB>>>(outp);
}

// round 14
// speedup vs baseline: 1.6906x; 1.6906x over previous
#include <cuda_runtime.h>
#include <cstdint>
#include <cstddef>

#define BB   2
#define NN   1024
#define DN   128
#define DE   16
#define MIDC 64
#define OUTC 128

// ---------------- scratch (static device arrays; no allocs) ----------------
__device__ __align__(16) float g_p1  [BB*NN*MIDC];   // features @ W1 (row-major, for prep_dots)
__device__ __align__(16) float g_p1F [BB*NN*MIDC];   // features @ W1, MMA-fragment-ordered tiles
__device__ __align__(16) float g_base[BB*NN*MIDC];   // features @ W2 + all biases + g@Wg (per-i)
__device__ __align__(16) float g_vals[BB*NN*OUTC];   // features @ Wm + bm
__device__ __align__(16) float g_skip[BB*NN*OUTC];   // features @ Wskip + bskip
__device__ float g_gw [BB*MIDC];                     // g_features @ Wg
__device__ float g_t  [BB*NN];                       // 0.505 * (p1_row . Wa)
__device__ float g_s2 [BB*NN];                       // ba + 0.505 * (base_row . Wa)
__device__ __align__(16) float g_wea[16];            // 0.505 * (We @ Wa)
__device__ __align__(16) float g_logits[BB*NN*NN];   // masked logits (8MB, L2-resident)
__device__ float g_rowmax[BB*NN];                    // per-row max of masked logits

typedef unsigned long long ull;

// ---------------- helpers ----------------
__device__ __forceinline__ uint32_t f2tf(float x) {
    uint32_t r; asm("cvt.rna.tf32.f32 %0, %1;" : "=r"(r) : "f"(x)); return r;
}
__device__ __forceinline__ ull pk2(float x, float y) {
    ull r; asm("mov.b64 %0, {%1, %2};" : "=l"(r) : "f"(x), "f"(y)); return r;
}
__device__ __forceinline__ ull dup2(float c) {
    ull r; asm("mov.b64 %0, {%1, %1};" : "=l"(r) : "f"(c)); return r;
}
__device__ __forceinline__ float2 upk(ull v) {
    float2 f; asm("mov.b64 {%0, %1}, %2;" : "=f"(f.x), "=f"(f.y) : "l"(v)); return f;
}
__device__ __forceinline__ void fma_x2(ull& d, ull a, ull b) {
    asm("fma.rn.f32x2 %0, %1, %2, %0;" : "+l"(d) : "l"(a), "l"(b));
}
__device__ __forceinline__ ull add_x2(ull a, ull b) {
    ull d; asm("add.rn.f32x2 %0, %1, %2;" : "=l"(d) : "l"(a), "l"(b)); return d;
}
__device__ __forceinline__ ull abs_x2(ull x) {
    ull r; asm("and.b64 %0, %1, 0x7FFFFFFF7FFFFFFF;" : "=l"(r) : "l"(x)); return r;
}
// m16n8k8 tf32 MMA on packed accumulators (c01 = row qid, c23 = row qid+8)
__device__ __forceinline__ void mma_p(ull& c01, ull& c23,
                                      const uint32_t a[4], uint32_t b0, uint32_t b1) {
    asm volatile("{\n\t"
        ".reg .f32 f0,f1,f2,f3;\n\t"
        "mov.b64 {f0,f1}, %0;\n\t"
        "mov.b64 {f2,f3}, %1;\n\t"
        "mma.sync.aligned.m16n8k8.row.col.f32.tf32.tf32.f32 "
        "{f0,f1,f2,f3}, {%2,%3,%4,%5}, {%6,%7}, {f0,f1,f2,f3};\n\t"
        "mov.b64 %0, {f0,f1};\n\t"
        "mov.b64 %1, {f2,f3};\n\t"
        "}" : "+l"(c01), "+l"(c23)
            : "r"(a[0]), "r"(a[1]), "r"(a[2]), "r"(a[3]), "r"(b0), "r"(b1));
}

// ---------------- prep 0: g@Wg and We@Wa ----------------
__global__ void prep_g(const float* __restrict__ gf, const float* __restrict__ Wg,
                       const float* __restrict__ We, const float* __restrict__ Wa) {
    int b = blockIdx.x;
    int t = threadIdx.x;
    if (t < MIDC) {
        float acc = 0.f;
        #pragma unroll 8
        for (int c = 0; c < DN; ++c) acc = fmaf(gf[b*DN + c], Wg[c*MIDC + t], acc);
        g_gw[b*MIDC + t] = acc;
    } else if (b == 0 && t < MIDC + DE) {
        int c = t - MIDC;
        float acc = 0.f;
        #pragma unroll
        for (int m = 0; m < MIDC; ++m) acc = fmaf(We[c*MIDC + m], Wa[m], acc);
        g_wea[c] = 0.505f * acc;
    }
}

// ---------------- prep 1: per-node linear terms, 16 rows per CTA ----------------
// block 384: t<128 -> Wm col, t<256 -> Wskip col, t<320 -> W1 col, t<384 -> W2 col
__global__ __launch_bounds__(384) void prep_all(
    const float* __restrict__ feat,
    const float* __restrict__ Wm,   const float* __restrict__ bm,
    const float* __restrict__ Wsk,  const float* __restrict__ bsk,
    const float* __restrict__ W1,   const float* __restrict__ b1,
    const float* __restrict__ W2,   const float* __restrict__ b2,
    const float* __restrict__ be,   const float* __restrict__ bg)
{
    __shared__ float sF[16*DN];
    const int r0 = blockIdx.x * 16;        // global row (b*N + n), multiple of 16
    const int b  = r0 / NN;
    const int t  = threadIdx.x;
    for (int x = t; x < 16*DN; x += 384) sF[x] = feat[(size_t)r0*DN + x];
    __syncthreads();

    const float* W; int stride, col;
    if      (t < 128) { W = Wm;  stride = OUTC; col = t;       }
    else if (t < 256) { W = Wsk; stride = OUTC; col = t - 128; }
    else if (t < 320) { W = W1;  stride = MIDC; col = t - 256; }
    else              { W = W2;  stride = MIDC; col = t - 320; }
    const float* wp = W + col;

    float acc[16];
    #pragma unroll
    for (int r = 0; r < 16; ++r) acc[r] = 0.f;
    #pragma unroll 4
    for (int c = 0; c < DN; ++c) {
        float wv = __ldg(wp + c*stride);
        #pragma unroll
        for (int r = 0; r < 16; ++r) acc[r] = fmaf(sF[r*DN + c], wv, acc[r]);
    }

    if (t < 128) {
        float bb = bm[col];
        #pragma unroll
        for (int r = 0; r < 16; ++r) g_vals[(size_t)(r0+r)*OUTC + col] = acc[r] + bb;
    } else if (t < 256) {
        float bb = bsk[col];
        #pragma unroll
        for (int r = 0; r < 16; ++r) g_skip[(size_t)(r0+r)*OUTC + col] = acc[r] + bb;
    } else if (t < 320) {
        // p1: write row-major (for prep_dots) AND MMA-fragment-ordered tile (for logits)
        #pragma unroll
        for (int r = 0; r < 16; ++r) {
            float val = acc[r];
            g_p1[(size_t)(r0+r)*MIDC + col] = val;
            int u    = ((r >> 3) << 2) | ((col & 15) >> 2);   // 0..7: rowhigh*4 + chunk
            int lane = ((r & 7) << 2) | (col >> 4);           // qid*4 + qt
            g_p1F[(size_t)(r0 >> 4)*1024 + u*128 + lane*4 + (col & 3)] = val;
        }
    } else {
        float bb = b1[col] + b2[col] + be[col] + bg[col] + g_gw[b*MIDC + col];
        #pragma unroll
        for (int r = 0; r < 16; ++r) g_base[(size_t)(r0+r)*MIDC + col] = acc[r] + bb;
    }
}

// ---------------- prep 2: per-row scalar dots with Wa ----------------
__global__ __launch_bounds__(256) void prep_dots(const float* __restrict__ Wa,
                                                 const float* __restrict__ ba) {
    const int w    = threadIdx.x >> 5;
    const int lane = threadIdx.x & 31;
    const int row  = blockIdx.x * 8 + w;       // 0 .. BB*NN-1
    float2 wa2 = ((const float2*)Wa)[lane];
    float2 pa  = ((const float2*)(g_p1   + (size_t)row*MIDC))[lane];
    float2 bb  = ((const float2*)(g_base + (size_t)row*MIDC))[lane];
    float vp = fmaf(pa.y, wa2.y, pa.x*wa2.x);
    float vb = fmaf(bb.y, wa2.y, bb.x*wa2.x);
    #pragma unroll
    for (int o = 16; o >= 1; o >>= 1) {
        vp += __shfl_xor_sync(0xffffffffu, vp, o);
        vb += __shfl_xor_sync(0xffffffffu, vb, o);
    }
    if (lane == 0) {
        g_t [row] = 0.505f * vp;
        g_s2[row] = ba[0] + 0.505f * vb;
    }
}

// ---------------- kernel A: masked logits + row max ----------------
// grid (NN/8, BB), block 256 (8 warps), warp = one i-row. 2 CTAs/SM.
__global__ __launch_bounds__(256, 2) void logits_kernel(
    const float* __restrict__ ef,   // (B,N,N,DE)
    const float* __restrict__ adj,  // (B,N,N)
    const float* __restrict__ We,   // (DE,MID)
    const float* __restrict__ Wa)   // (MID,1)
{
    __shared__ float sWaN[MIDC];    // 0.495 * Wa
    const int b    = blockIdx.y;
    const int tid  = threadIdx.x;
    const int w    = tid >> 5;
    const int lane = tid & 31;
    const int qid  = lane >> 2;
    const int qt   = lane & 3;
    const int i    = blockIdx.x*8 + w;

    if (tid < MIDC) sWaN[tid] = 0.495f * Wa[tid];
    __syncthreads();

    // We fragments under permutations (k: c = 4q+2s+h ; n: m = 16*qt' + 2*nt + r)
    uint32_t bf0[8][2], bf1[8][2];
    {
        const int colb = 16*(qid >> 1) + (qid & 1);
        #pragma unroll
        for (int nt = 0; nt < 8; ++nt) {
            bf0[nt][0] = f2tf(We[(4*qt + 0)*MIDC + colb + 2*nt]);
            bf0[nt][1] = f2tf(We[(4*qt + 1)*MIDC + colb + 2*nt]);
            bf1[nt][0] = f2tf(We[(4*qt + 2)*MIDC + colb + 2*nt]);
            bf1[nt][1] = f2tf(We[(4*qt + 3)*MIDC + colb + 2*nt]);
        }
    }
    ull bse[8];
    {
        const ull* bp = (const ull*)(g_base + (size_t)(b*NN + i)*MIDC);
        #pragma unroll
        for (int nt = 0; nt < 8; ++nt) bse[nt] = bp[8*qt + nt];
    }
    const float  sI   = g_s2[b*NN + i];
    const float4 wea  = ((const float4*)g_wea)[qt];
    const float* __restrict__ tb     = g_t + b*NN;
    const float* __restrict__ adjrow = adj + (size_t)(b*NN + i)*NN;
    const float4* __restrict__ er    = (const float4*)ef + (size_t)(b*NN + i)*NN*(DE/4);
    float* __restrict__ lrow         = g_logits + (size_t)(b*NN + i)*NN;
    // tile stride: 1024 floats = 256 ulonglong2 per 16-row tile
    const ulonglong2* __restrict__ pF = (const ulonglong2*)g_p1F + (size_t)b*(NN/16)*256;

    // depth-1 prefetch of DRAM operands
    float4 eA = __ldg(er + (size_t)qid*(DE/4) + qt);
    float4 eB = __ldg(er + (size_t)(qid + 8)*(DE/4) + qt);
    float  ad0 = __ldg(adjrow + qid);
    float  ad1 = __ldg(adjrow + qid + 8);
    float  mx  = -3.0e38f;

    #pragma unroll 1
    for (int jt = 0; jt < NN/16; ++jt) {
        const int j0 = jt*16 + qid;

        // p1 fragment loads: fully coalesced LDG.128 from pre-swizzled tile
        const ulonglong2* pj = pF + (size_t)jt*256;
        ull p1a[8], p1b[8];
        #pragma unroll
        for (int v = 0; v < 4; ++v) {
            ulonglong2 A  = __ldg(pj + v*32 + lane);        // row j0 (qid), ch 16qt+4v..+3
            ulonglong2 Bv = __ldg(pj + (4+v)*32 + lane);    // row j0+8
            p1a[2*v] = A.x;  p1a[2*v+1] = A.y;
            p1b[2*v] = Bv.x; p1b[2*v+1] = Bv.y;
        }

        const int jb = (jt < NN/16 - 1) ? (jt+1)*16 + qid : j0;
        float4 nA = __ldg(er + (size_t)jb*(DE/4) + qt);
        float4 nB = __ldg(er + (size_t)(jb + 8)*(DE/4) + qt);
        float  nd0 = __ldg(adjrow + jb);
        float  nd1 = __ldg(adjrow + jb + 8);

        uint32_t aS0[4] = { f2tf(eA.x), f2tf(eB.x), f2tf(eA.y), f2tf(eB.y) };
        uint32_t aS1[4] = { f2tf(eA.z), f2tf(eB.z), f2tf(eA.w), f2tf(eB.w) };

        ull P0 = 0ull, P1 = 0ull;
        #pragma unroll
        for (int nt = 0; nt < 8; ++nt) {
            ull wn = ((const ull*)sWaN)[8*qt + nt];
            ull c01 = add_x2(bse[nt], p1a[nt]);
            ull c23 = add_x2(bse[nt], p1b[nt]);
            mma_p(c01, c23, aS0, bf0[nt][0], bf0[nt][1]);
            mma_p(c01, c23, aS1, bf1[nt][0], bf1[nt][1]);
            fma_x2(P0, wn, abs_x2(c01));
            fma_x2(P1, wn, abs_x2(c23));
        }
        float lin0 = fmaf(eA.w, wea.w, fmaf(eA.z, wea.z, fmaf(eA.y, wea.y, eA.x*wea.x)));
        float lin1 = fmaf(eB.w, wea.w, fmaf(eB.z, wea.z, fmaf(eB.y, wea.y, eB.x*wea.x)));
        float2 u0 = upk(P0), u1 = upk(P1);
        float acc0 = u0.x + u0.y + lin0;
        float acc1 = u1.x + u1.y + lin1;
        acc0 += __shfl_xor_sync(0xffffffffu, acc0, 1);
        acc0 += __shfl_xor_sync(0xffffffffu, acc0, 2);
        acc1 += __shfl_xor_sync(0xffffffffu, acc1, 1);
        acc1 += __shfl_xor_sync(0xffffffffu, acc1, 2);
        if (qt == 0) {
            float l0 = acc0 + sI + tb[j0]   + (ad0 - 1.0f)*1e9f;
            float l1 = acc1 + sI + tb[j0+8] + (ad1 - 1.0f)*1e9f;
            lrow[j0]     = l0;
            lrow[j0 + 8] = l1;
            mx = fmaxf(mx, fmaxf(l0, l1));
        }
        eA = nA; eB = nB; ad0 = nd0; ad1 = nd1;
    }
    // reduce max over the 8 qt==0 lanes (lanes 0,4,...,28)
    mx = fmaxf(mx, __shfl_xor_sync(0xffffffffu, mx, 4));
    mx = fmaxf(mx, __shfl_xor_sync(0xffffffffu, mx, 8));
    mx = fmaxf(mx, __shfl_xor_sync(0xffffffffu, mx, 16));
    if (lane == 0) g_rowmax[b*NN + i] = mx;
}

// ---------------- kernel B: exp/softmax + coefs@values + skip + relu ----------------
// grid (NN/16, BB), block 256 (8 warps, 2 rows/warp). smem: sE 64KB + sV 16KB (double-buffered).
__global__ __launch_bounds__(256) void aggregate_kernel(float* __restrict__ outp)
{
    extern __shared__ float smB[];
    float* sE = smB;                    // 16 * NN  exp values
    float* sV = smB + 16*NN;            // 2 * 16 * OUTC  value tiles
    const int b    = blockIdx.y;
    const int it0  = blockIdx.x * 16;
    const int tid  = threadIdx.x;
    const int w    = tid >> 5;
    const int lane = tid & 31;
    const int r0   = 2*w, r1 = 2*w + 1;

    // exp phase (warp-private rows; ordered vs reads by the __syncthreads below)
    float inv[2];
    #pragma unroll
    for (int il = 0; il < 2; ++il) {
        const int i = it0 + 2*w + il;
        const float mxv = g_rowmax[b*NN + i];
        const float4* lr = (const float4*)(g_logits + (size_t)(b*NN + i)*NN);
        float4* se = (float4*)(sE + (2*w + il)*NN);
        float s = 0.f;
        #pragma unroll
        for (int t = 0; t < 8; ++t) {
            float4 L = __ldg(lr + lane + 32*t);
            float4 E;
            E.x = __expf(L.x - mxv); E.y = __expf(L.y - mxv);
            E.z = __expf(L.z - mxv); E.w = __expf(L.w - mxv);
            se[lane + 32*t] = E;
            s += (E.x + E.y) + (E.z + E.w);
        }
        #pragma unroll
        for (int o = 16; o >= 1; o >>= 1) s += __shfl_xor_sync(0xffffffffu, s, o);
        inv[il] = 1.0f / s;
    }

    // aggregation with double-buffered value tiles (16 j x 128 ch per tile)
    const float4* v4 = (const float4*)g_vals + (size_t)b*NN*(OUTC/4);
    {
        #pragma unroll
        for (int k = 0; k < 2; ++k) {
            int f = 2*tid + k; int jr = f >> 5, fc = f & 31;
            ((float4*)sV)[f] = __ldg(v4 + (size_t)jr*(OUTC/4) + fc);
        }
    }
    __syncthreads();

    ull a00 = 0ull, a01 = 0ull, a10 = 0ull, a11 = 0ull;
    #pragma unroll 1
    for (int jt = 0; jt < NN/16; ++jt) {
        const int cur = jt & 1;
        float4 pre0, pre1;
        if (jt < NN/16 - 1) {
            int f0 = 2*tid, f1 = 2*tid + 1;
            pre0 = __ldg(v4 + (size_t)((jt+1)*16 + (f0 >> 5))*(OUTC/4) + (f0 & 31));
            pre1 = __ldg(v4 + (size_t)((jt+1)*16 + (f1 >> 5))*(OUTC/4) + (f1 & 31));
        }
        const float* e0p = sE + r0*NN + jt*16;
        const float* e1p = sE + r1*NN + jt*16;
        const float4* vb = (const float4*)(sV + cur*(16*OUTC));
        #pragma unroll
        for (int jj = 0; jj < 16; ++jj) {
            float4 v = vb[jj*(OUTC/4) + lane];
            ull v01 = pk2(v.x, v.y), v23 = pk2(v.z, v.w);
            ull c0 = dup2(e0p[jj]);
            ull c1 = dup2(e1p[jj]);
            fma_x2(a00, v01, c0);  fma_x2(a01, v23, c0);
            fma_x2(a10, v01, c1);  fma_x2(a11, v23, c1);
        }
        if (jt < NN/16 - 1) {
            float4* dst = (float4*)(sV + (cur ^ 1)*(16*OUTC));
            dst[2*tid]     = pre0;
            dst[2*tid + 1] = pre1;
            __syncthreads();
        }
    }

    // epilogue
    #pragma unroll
    for (int il = 0; il < 2; ++il) {
        size_t row = (size_t)(b*NN + it0 + 2*w + il);
        float2 x0 = upk(il ? a10 : a00);
        float2 x1 = upk(il ? a11 : a01);
        float4 sk = __ldg((const float4*)g_skip + row*(OUTC/4) + lane);
        float4 o;
        o.x = fmaxf(fmaf(x0.x, inv[il], sk.x), 0.f);
        o.y = fmaxf(fmaf(x0.y, inv[il], sk.y), 0.f);
        o.z = fmaxf(fmaf(x1.x, inv[il], sk.z), 0.f);
        o.w = fmaxf(fmaf(x1.y, inv[il], sk.w), 0.f);
        ((float4*)outp)[row*(OUTC/4) + lane] = o;
    }
}

// ---------------- launch ----------------
extern "C" void kernel_launch(void* const* d_in, const int* in_sizes, int n_in,
                              void* d_out, int out_size)
{
    const float* features   = (const float*)d_in[0];
    const float* e_features = (const float*)d_in[1];
    const float* g_features = (const float*)d_in[2];
    const float* adj        = (const float*)d_in[3];
    const float* Wm         = (const float*)d_in[4];
    const float* bm         = (const float*)d_in[5];
    const float* Wskip      = (const float*)d_in[6];
    const float* bskip      = (const float*)d_in[7];
    const float* W1         = (const float*)d_in[8];
    const float* b1         = (const float*)d_in[9];
    const float* W2         = (const float*)d_in[10];
    const float* b2         = (const float*)d_in[11];
    const float* We         = (const float*)d_in[12];
    const float* be         = (const float*)d_in[13];
    const float* Wg         = (const float*)d_in[14];
    const float* bg         = (const float*)d_in[15];
    const float* Wa         = (const float*)d_in[16];
    const float* ba         = (const float*)d_in[17];
    float* outp = (float*)d_out;

    const int smemB = (16*NN + 2*16*OUTC) * (int)sizeof(float);   // 81920
    cudaFuncSetAttribute(aggregate_kernel, cudaFuncAttributeMaxDynamicSharedMemorySize, smemB);

    prep_g   <<<BB, MIDC + DE + 16>>>(g_features, Wg, We, Wa);
    prep_all <<<BB*NN/16, 384>>>(features, Wm, bm, Wskip, bskip, W1, b1, W2, b2, be, bg);
    prep_dots<<<BB*NN/8, 256>>>(Wa, ba);

    dim3 gridA(NN/8, BB);
    logits_kernel<<<gridA, 256>>>(e_features, adj, We, Wa);

    dim3 gridB(NN/16, BB);
    aggregate_kernel<<<gridB, 256, smemB>>>(outp);
}